// round 3
// baseline (speedup 1.0000x reference)
#include <cuda_runtime.h>
#include <cuda_bf16.h>
#include <math.h>
#include <stdint.h>

// ---------------- problem constants ----------------
#define TT   4096
#define HH   2048
#define EE   64
#define MM   1408
#define MSS  2816
#define KK   6
#define CC   768
#define NGG  8
#define TGG  3
#define NPAIR (TT*KK)        // 24576

// ---------------- device scratch ----------------
__device__ int   g_topk_i[NPAIR];
__device__ float g_topk_w[NPAIR];
__device__ int   g_cnt[EE];
__device__ int   g_lists[EE*CC];

// bf16 hi/lo splits
__device__ __nv_bfloat16 g_xh[(size_t)TT*HH];
__device__ __nv_bfloat16 g_xl[(size_t)TT*HH];
__device__ __nv_bfloat16 g_Wgh[(size_t)EE*MM*HH];
__device__ __nv_bfloat16 g_Wgl[(size_t)EE*MM*HH];
__device__ __nv_bfloat16 g_Wuh[(size_t)EE*MM*HH];
__device__ __nv_bfloat16 g_Wul[(size_t)EE*MM*HH];
__device__ __nv_bfloat16 g_Wdh[(size_t)EE*HH*MM];
__device__ __nv_bfloat16 g_Wdl[(size_t)EE*HH*MM];
__device__ __nv_bfloat16 g_Sgh[(size_t)MSS*HH];
__device__ __nv_bfloat16 g_Sgl[(size_t)MSS*HH];
__device__ __nv_bfloat16 g_Suh[(size_t)MSS*HH];
__device__ __nv_bfloat16 g_Sul[(size_t)MSS*HH];
__device__ __nv_bfloat16 g_Sdh[(size_t)HH*MSS];
__device__ __nv_bfloat16 g_Sdl[(size_t)HH*MSS];

// intermediates
__device__ float g_gbuf[(size_t)NPAIR*MM];
__device__ float g_ubuf[(size_t)NPAIR*MM];
__device__ __nv_bfloat16 g_hh[(size_t)NPAIR*MM];
__device__ __nv_bfloat16 g_hl[(size_t)NPAIR*MM];
__device__ float g_outb[(size_t)NPAIR*HH];
__device__ float g_gs[(size_t)TT*MSS];
__device__ float g_us[(size_t)TT*MSS];
__device__ __nv_bfloat16 g_hsh[(size_t)TT*MSS];
__device__ __nv_bfloat16 g_hsl[(size_t)TT*MSS];
__device__ float g_ys[(size_t)TT*HH];

// ---------------- gate ----------------
__global__ void gate_kernel(const float* __restrict__ x,
                            const float* __restrict__ gw,
                            int* __restrict__ ti, float* __restrict__ tw)
{
    int t = blockIdx.x;
    __shared__ float xs[HH];
    __shared__ float sc[EE];
    for (int i = threadIdx.x; i < HH; i += 64) xs[i] = x[(size_t)t*HH + i];
    __syncthreads();
    {
        int e = threadIdx.x;
        const float* w = gw + (size_t)e * HH;
        float acc = 0.f;
        #pragma unroll 8
        for (int h = 0; h < HH; ++h) acc = fmaf(xs[h], w[h], acc);
        sc[e] = acc;
    }
    __syncthreads();
    if (threadIdx.x == 0) {
        float mx = sc[0];
        for (int e = 1; e < EE; ++e) mx = fmaxf(mx, sc[e]);
        float sum = 0.f;
        for (int e = 0; e < EE; ++e) { float v = expf(sc[e] - mx); sc[e] = v; sum += v; }
        float inv = 1.f / sum;
        for (int e = 0; e < EE; ++e) sc[e] *= inv;
        float gs[NGG];
        for (int g = 0; g < NGG; ++g) {
            float m = sc[g*8];
            for (int j = 1; j < 8; ++j) m = fmaxf(m, sc[g*8 + j]);
            gs[g] = m;
        }
        unsigned gsel = 0;
        for (int it = 0; it < TGG; ++it) {
            int best = -1; float bv = -1e30f;
            for (int g = 0; g < NGG; ++g)
                if (!((gsel >> g) & 1u) && gs[g] > bv) { bv = gs[g]; best = g; }
            gsel |= 1u << best;
        }
        unsigned long long used = 0ull;
        for (int kk = 0; kk < KK; ++kk) {
            int best = -1; float bv = -1e30f;
            for (int e = 0; e < EE; ++e) {
                if (!((gsel >> (e >> 3)) & 1u)) continue;
                if ((used >> e) & 1ull) continue;
                if (sc[e] > bv) { bv = sc[e]; best = e; }
            }
            used |= 1ull << best;
            ti[t*KK + kk] = best;
            tw[t*KK + kk] = sc[best];
        }
    }
}

__global__ void zero_cnt_kernel() { if (threadIdx.x < EE) g_cnt[threadIdx.x] = 0; }

__global__ void dispatch_kernel(const int* __restrict__ ti)
{
    int p = blockIdx.x * blockDim.x + threadIdx.x;
    if (p >= NPAIR) return;
    int e = ti[p];
    int r = atomicAdd(&g_cnt[e], 1);
    if (r < CC) g_lists[e*CC + r] = p;
}

// ---------------- fp32 -> bf16 hi/lo split (vectorized x4) ----------------
__global__ void split4_kernel(const float4* __restrict__ src,
                              __nv_bfloat162* __restrict__ hi,
                              __nv_bfloat162* __restrict__ lo, size_t n4)
{
    size_t i = (size_t)blockIdx.x * blockDim.x + threadIdx.x;
    size_t stride = (size_t)gridDim.x * blockDim.x;
    for (; i < n4; i += stride) {
        float4 v = src[i];
        __nv_bfloat16 hx = __float2bfloat16(v.x), hy = __float2bfloat16(v.y);
        __nv_bfloat16 hz = __float2bfloat16(v.z), hw = __float2bfloat16(v.w);
        __nv_bfloat16 lx = __float2bfloat16(v.x - __bfloat162float(hx));
        __nv_bfloat16 ly = __float2bfloat16(v.y - __bfloat162float(hy));
        __nv_bfloat16 lz = __float2bfloat16(v.z - __bfloat162float(hz));
        __nv_bfloat16 lw = __float2bfloat16(v.w - __bfloat162float(hw));
        hi[i*2+0] = __nv_bfloat162(hx, hy);
        hi[i*2+1] = __nv_bfloat162(hz, hw);
        lo[i*2+0] = __nv_bfloat162(lx, ly);
        lo[i*2+1] = __nv_bfloat162(lz, lw);
    }
}

// ---------------- swiglu fuse + split ----------------
__global__ void swiglu_split_kernel(const float* __restrict__ g,
                                    const float* __restrict__ u,
                                    __nv_bfloat16* __restrict__ hi,
                                    __nv_bfloat16* __restrict__ lo, size_t n)
{
    size_t i = ((size_t)blockIdx.x * blockDim.x + threadIdx.x) * 4;
    size_t stride = (size_t)gridDim.x * blockDim.x * 4;
    for (; i < n; i += stride) {
        #pragma unroll
        for (int j = 0; j < 4; ++j) {
            float gv = g[i+j];
            float v = (gv / (1.f + expf(-gv))) * u[i+j];
            __nv_bfloat16 h = __float2bfloat16(v);
            hi[i+j] = h;
            lo[i+j] = __float2bfloat16(v - __bfloat162float(h));
        }
    }
}

// ---------------- bf16 split-MMA GEMM ----------------
// C[m,n] = sum_k A[row(m),k]*B[e][n,k], A=Ah+Al, B=Bh+Bl, 3-pass split.
// CTA 128x128x32, 8 warps of 64x32, 3-stage cp.async pipeline.

__device__ __forceinline__ void cp_async16(uint32_t dst, const void* src, int srcsize) {
    asm volatile("cp.async.cg.shared.global [%0], [%1], 16, %2;\n"
                 :: "r"(dst), "l"(src), "r"(srcsize));
}
__device__ __forceinline__ void cp_commit() { asm volatile("cp.async.commit_group;\n" ::); }

#define LDSM4(R, addr) asm volatile( \
    "ldmatrix.sync.aligned.m8n8.x4.shared.b16 {%0,%1,%2,%3},[%4];" \
    : "=r"((R)[0]), "=r"((R)[1]), "=r"((R)[2]), "=r"((R)[3]) : "r"(addr))
#define LDSM2(R, addr) asm volatile( \
    "ldmatrix.sync.aligned.m8n8.x2.shared.b16 {%0,%1},[%2];" \
    : "=r"((R)[0]), "=r"((R)[1]) : "r"(addr))
#define MMA16816(C, A, B) asm volatile( \
    "mma.sync.aligned.m16n8k16.row.col.f32.bf16.bf16.f32 " \
    "{%0,%1,%2,%3},{%4,%5,%6,%7},{%8,%9},{%0,%1,%2,%3};" \
    : "+f"((C)[0]), "+f"((C)[1]), "+f"((C)[2]), "+f"((C)[3]) \
    : "r"((A)[0]), "r"((A)[1]), "r"((A)[2]), "r"((A)[3]), "r"((B)[0]), "r"((B)[1]))

#define SMEM_STAGE 40960            // 4 arrays * 128 rows * 80B
#define SMEM_TOTAL (3*SMEM_STAGE + 1024)

template<bool GATHER>
__global__ void __launch_bounds__(256, 1)
mma_gemm(const __nv_bfloat16* __restrict__ Ah, const __nv_bfloat16* __restrict__ Al,
         const __nv_bfloat16* __restrict__ Bhg, const __nv_bfloat16* __restrict__ Blg,
         float* __restrict__ Out,
         int Kd, int adiv, long long bstride, int ldOut, int nrows_fixed)
{
    extern __shared__ char smem[];
    const int e = blockIdx.z;
    int nrows;
    const int* mylist = nullptr;
    if (GATHER) { nrows = min(g_cnt[e], CC); mylist = &g_lists[e*CC]; }
    else        { nrows = nrows_fixed; }
    const int m0 = blockIdx.y * 128;
    if (m0 >= nrows) return;
    const int n0 = blockIdx.x * 128;

    const __nv_bfloat16* Bh = Bhg + (size_t)e * bstride;
    const __nv_bfloat16* Bl = Blg + (size_t)e * bstride;

    int* rowA = (int*)(smem + 3*SMEM_STAGE);
    int* rowO = (int*)(smem + 3*SMEM_STAGE + 512);

    const int tid = threadIdx.x;
    if (tid < 128) {
        int r = m0 + tid;
        if (r < nrows) {
            if (GATHER) { int p = mylist[r]; rowA[tid] = p / adiv; rowO[tid] = p; }
            else        { rowA[tid] = r; rowO[tid] = r; }
        } else { rowA[tid] = -1; rowO[tid] = -1; }
    }
    __syncthreads();

    const uint32_t smem_u = (uint32_t)__cvta_generic_to_shared(smem);

    // loader: each thread does 2 chunks per array (512 chunks = 128 rows x 4)
    const int ch0 = tid * 2;
    const int lr0 = ch0 >> 2, lc0 = (ch0 & 3) * 16;
    const int lr1 = (ch0+1) >> 2, lc1 = ((ch0+1) & 3) * 16;

    auto load_stage = [&](int s, int kt) {
        const uint32_t b = smem_u + s * SMEM_STAGE;
        const int k0 = kt * 32;
        {
            int ra = rowA[lr0]; int sz = (ra < 0) ? 0 : 16; int rsafe = (ra < 0) ? 0 : ra;
            const char* pah = (const char*)(Ah + (size_t)rsafe*Kd + k0) + lc0;
            const char* pal = (const char*)(Al + (size_t)rsafe*Kd + k0) + lc0;
            uint32_t d = b + lr0*80 + lc0;
            cp_async16(d, pah, sz);
            cp_async16(d + 10240, pal, sz);
            const char* pbh = (const char*)(Bh + (size_t)(n0+lr0)*Kd + k0) + lc0;
            const char* pbl = (const char*)(Bl + (size_t)(n0+lr0)*Kd + k0) + lc0;
            cp_async16(d + 20480, pbh, 16);
            cp_async16(d + 30720, pbl, 16);
        }
        {
            int ra = rowA[lr1]; int sz = (ra < 0) ? 0 : 16; int rsafe = (ra < 0) ? 0 : ra;
            const char* pah = (const char*)(Ah + (size_t)rsafe*Kd + k0) + lc1;
            const char* pal = (const char*)(Al + (size_t)rsafe*Kd + k0) + lc1;
            uint32_t d = b + lr1*80 + lc1;
            cp_async16(d, pah, sz);
            cp_async16(d + 10240, pal, sz);
            const char* pbh = (const char*)(Bh + (size_t)(n0+lr1)*Kd + k0) + lc1;
            const char* pbl = (const char*)(Bl + (size_t)(n0+lr1)*Kd + k0) + lc1;
            cp_async16(d + 20480, pbh, 16);
            cp_async16(d + 30720, pbl, 16);
        }
        cp_commit();
    };

    const int lane = tid & 31;
    const int wid  = tid >> 5;
    const int wm = (wid & 1) * 64;       // warp m offset
    const int wn = (wid >> 1) * 32;      // warp n offset

    float acc[4][4][4];
    #pragma unroll
    for (int i = 0; i < 4; ++i)
        #pragma unroll
        for (int j = 0; j < 4; ++j)
            #pragma unroll
            for (int c = 0; c < 4; ++c) acc[i][j][c] = 0.f;

    const int KT = Kd / 32;
    load_stage(0, 0);
    load_stage(1, 1);

    // ldmatrix base offsets (bytes within an array)
    const uint32_t aoff = (uint32_t)((wm + (lane & 7) + ((lane >> 3) & 1) * 8) * 80
                                     + ((lane >> 4) * 8) * 2);
    const uint32_t boff = (uint32_t)((wn + (lane & 7)) * 80 + (((lane >> 3) & 1) * 8) * 2);

    for (int kt = 0; kt < KT; ++kt) {
        asm volatile("cp.async.wait_group 1;\n" ::);
        __syncthreads();
        if (kt + 2 < KT) load_stage((kt + 2) % 3, kt + 2);
        else cp_commit();   // keep group numbering consistent

        const uint32_t b = smem_u + (kt % 3) * SMEM_STAGE;
        #pragma unroll
        for (int kk = 0; kk < 2; ++kk) {
            const uint32_t kb = kk * 32;   // 16 elems * 2B
            uint32_t ah[4][4], al[4][4], bh[4][2], bl[4][2];
            #pragma unroll
            for (int mi = 0; mi < 4; ++mi) {
                LDSM4(ah[mi], b + aoff + kb + mi * (16*80));
                LDSM4(al[mi], b + 10240 + aoff + kb + mi * (16*80));
            }
            #pragma unroll
            for (int ni = 0; ni < 4; ++ni) {
                LDSM2(bh[ni], b + 20480 + boff + kb + ni * (8*80));
                LDSM2(bl[ni], b + 30720 + boff + kb + ni * (8*80));
            }
            #pragma unroll
            for (int mi = 0; mi < 4; ++mi)
                #pragma unroll
                for (int ni = 0; ni < 4; ++ni) {
                    MMA16816(acc[mi][ni], ah[mi], bh[ni]);
                    MMA16816(acc[mi][ni], ah[mi], bl[ni]);
                    MMA16816(acc[mi][ni], al[mi], bh[ni]);
                }
        }
        __syncthreads();
    }
    asm volatile("cp.async.wait_group 0;\n" ::);

    // epilogue
    const int g4 = lane >> 2, tig = lane & 3;
    #pragma unroll
    for (int mi = 0; mi < 4; ++mi) {
        int r0 = wm + mi*16 + g4;
        int r1 = r0 + 8;
        int o0 = rowO[r0], o1 = rowO[r1];
        #pragma unroll
        for (int ni = 0; ni < 4; ++ni) {
            int cc = n0 + wn + ni*8 + tig*2;
            if (o0 >= 0) {
                float2* p = (float2*)(Out + (size_t)o0*ldOut + cc);
                *p = make_float2(acc[mi][ni][0], acc[mi][ni][1]);
            }
            if (o1 >= 0) {
                float2* p = (float2*)(Out + (size_t)o1*ldOut + cc);
                *p = make_float2(acc[mi][ni][2], acc[mi][ni][3]);
            }
        }
    }
}

// ---------------- combine ----------------
__global__ void combine_kernel(const float* __restrict__ ob,
                               const float* __restrict__ ys,
                               const float* __restrict__ tw,
                               float* __restrict__ y)
{
    int t = blockIdx.x;
    for (int c = threadIdx.x; c < HH; c += blockDim.x) {
        float acc = ys[(size_t)t*HH + c];
        #pragma unroll
        for (int k = 0; k < KK; ++k) {
            int p = t*KK + k;
            acc = fmaf(tw[p], ob[(size_t)p*HH + c], acc);
        }
        y[(size_t)t*HH + c] = acc;
    }
}

// ---------------- launch ----------------
static void launch_split(const float* src, __nv_bfloat16* hi, __nv_bfloat16* lo, size_t n) {
    size_t n4 = n / 4;
    int blocks = (int)((n4 + 255) / 256);
    if (blocks > 65535*8) blocks = 65535*8;
    split4_kernel<<<blocks, 256>>>((const float4*)src, (__nv_bfloat162*)hi,
                                   (__nv_bfloat162*)lo, n4);
}

extern "C" void kernel_launch(void* const* d_in, const int* in_sizes, int n_in,
                              void* d_out, int out_size)
{
    const float* x  = (const float*)d_in[0];
    const float* gw = (const float*)d_in[1];
    const float* Wg = (const float*)d_in[2];
    const float* Wu = (const float*)d_in[3];
    const float* Wd = (const float*)d_in[4];
    const float* Sg = (const float*)d_in[5];
    const float* Su = (const float*)d_in[6];
    const float* Sd = (const float*)d_in[7];
    float* y = (float*)d_out;

    // symbol addresses
    void *p_ti, *p_tw;
    void *p_xh, *p_xl, *p_Wgh, *p_Wgl, *p_Wuh, *p_Wul, *p_Wdh, *p_Wdl;
    void *p_Sgh, *p_Sgl, *p_Suh, *p_Sul, *p_Sdh, *p_Sdl;
    void *p_g, *p_u, *p_hh, *p_hl, *p_ob, *p_gs, *p_us, *p_hsh, *p_hsl, *p_ys;
    cudaGetSymbolAddress(&p_ti, g_topk_i);  cudaGetSymbolAddress(&p_tw, g_topk_w);
    cudaGetSymbolAddress(&p_xh, g_xh);      cudaGetSymbolAddress(&p_xl, g_xl);
    cudaGetSymbolAddress(&p_Wgh, g_Wgh);    cudaGetSymbolAddress(&p_Wgl, g_Wgl);
    cudaGetSymbolAddress(&p_Wuh, g_Wuh);    cudaGetSymbolAddress(&p_Wul, g_Wul);
    cudaGetSymbolAddress(&p_Wdh, g_Wdh);    cudaGetSymbolAddress(&p_Wdl, g_Wdl);
    cudaGetSymbolAddress(&p_Sgh, g_Sgh);    cudaGetSymbolAddress(&p_Sgl, g_Sgl);
    cudaGetSymbolAddress(&p_Suh, g_Suh);    cudaGetSymbolAddress(&p_Sul, g_Sul);
    cudaGetSymbolAddress(&p_Sdh, g_Sdh);    cudaGetSymbolAddress(&p_Sdl, g_Sdl);
    cudaGetSymbolAddress(&p_g, g_gbuf);     cudaGetSymbolAddress(&p_u, g_ubuf);
    cudaGetSymbolAddress(&p_hh, g_hh);      cudaGetSymbolAddress(&p_hl, g_hl);
    cudaGetSymbolAddress(&p_ob, g_outb);
    cudaGetSymbolAddress(&p_gs, g_gs);      cudaGetSymbolAddress(&p_us, g_us);
    cudaGetSymbolAddress(&p_hsh, g_hsh);    cudaGetSymbolAddress(&p_hsl, g_hsl);
    cudaGetSymbolAddress(&p_ys, g_ys);

    cudaFuncSetAttribute(mma_gemm<true>,  cudaFuncAttributeMaxDynamicSharedMemorySize, SMEM_TOTAL);
    cudaFuncSetAttribute(mma_gemm<false>, cudaFuncAttributeMaxDynamicSharedMemorySize, SMEM_TOTAL);

    // 1) gate + dispatch
    gate_kernel<<<TT, 64>>>(x, gw, (int*)p_ti, (float*)p_tw);
    zero_cnt_kernel<<<1, 64>>>();
    dispatch_kernel<<<(NPAIR + 255)/256, 256>>>((const int*)p_ti);

    // 2) splits
    launch_split(x,  (__nv_bfloat16*)p_xh,  (__nv_bfloat16*)p_xl,  (size_t)TT*HH);
    launch_split(Wg, (__nv_bfloat16*)p_Wgh, (__nv_bfloat16*)p_Wgl, (size_t)EE*MM*HH);
    launch_split(Wu, (__nv_bfloat16*)p_Wuh, (__nv_bfloat16*)p_Wul, (size_t)EE*MM*HH);
    launch_split(Wd, (__nv_bfloat16*)p_Wdh, (__nv_bfloat16*)p_Wdl, (size_t)EE*HH*MM);
    launch_split(Sg, (__nv_bfloat16*)p_Sgh, (__nv_bfloat16*)p_Sgl, (size_t)MSS*HH);
    launch_split(Su, (__nv_bfloat16*)p_Suh, (__nv_bfloat16*)p_Sul, (size_t)MSS*HH);
    launch_split(Sd, (__nv_bfloat16*)p_Sdh, (__nv_bfloat16*)p_Sdl, (size_t)HH*MSS);

    // 3) routed GEMM1: g and u  (A = gathered x rows, K = HH)
    mma_gemm<true><<<dim3(MM/128, CC/128, EE), 256, SMEM_TOTAL>>>(
        (const __nv_bfloat16*)p_xh, (const __nv_bfloat16*)p_xl,
        (const __nv_bfloat16*)p_Wgh, (const __nv_bfloat16*)p_Wgl,
        (float*)p_g, HH, KK, (long long)MM*HH, MM, 0);
    mma_gemm<true><<<dim3(MM/128, CC/128, EE), 256, SMEM_TOTAL>>>(
        (const __nv_bfloat16*)p_xh, (const __nv_bfloat16*)p_xl,
        (const __nv_bfloat16*)p_Wuh, (const __nv_bfloat16*)p_Wul,
        (float*)p_u, HH, KK, (long long)MM*HH, MM, 0);

    // 4) swiglu fuse + split
    {
        size_t n = (size_t)NPAIR*MM;
        int blocks = (int)((n/4 + 255)/256);
        swiglu_split_kernel<<<blocks, 256>>>((const float*)p_g, (const float*)p_u,
                                             (__nv_bfloat16*)p_hh, (__nv_bfloat16*)p_hl, n);
    }

    // 5) routed GEMM2: Wd  (A = h rows by pair id, K = MM)
    mma_gemm<true><<<dim3(HH/128, CC/128, EE), 256, SMEM_TOTAL>>>(
        (const __nv_bfloat16*)p_hh, (const __nv_bfloat16*)p_hl,
        (const __nv_bfloat16*)p_Wdh, (const __nv_bfloat16*)p_Wdl,
        (float*)p_ob, MM, 1, (long long)HH*MM, HH, 0);

    // 6) shared expert: g, u GEMMs (K = HH)
    mma_gemm<false><<<dim3(MSS/128, TT/128, 1), 256, SMEM_TOTAL>>>(
        (const __nv_bfloat16*)p_xh, (const __nv_bfloat16*)p_xl,
        (const __nv_bfloat16*)p_Sgh, (const __nv_bfloat16*)p_Sgl,
        (float*)p_gs, HH, 1, 0LL, MSS, TT);
    mma_gemm<false><<<dim3(MSS/128, TT/128, 1), 256, SMEM_TOTAL>>>(
        (const __nv_bfloat16*)p_xh, (const __nv_bfloat16*)p_xl,
        (const __nv_bfloat16*)p_Suh, (const __nv_bfloat16*)p_Sul,
        (float*)p_us, HH, 1, 0LL, MSS, TT);

    // 7) shared swiglu
    {
        size_t n = (size_t)TT*MSS;
        int blocks = (int)((n/4 + 255)/256);
        swiglu_split_kernel<<<blocks, 256>>>((const float*)p_gs, (const float*)p_us,
                                             (__nv_bfloat16*)p_hsh, (__nv_bfloat16*)p_hsl, n);
    }

    // 8) shared GEMM2 (K = MSS)
    mma_gemm<false><<<dim3(HH/128, TT/128, 1), 256, SMEM_TOTAL>>>(
        (const __nv_bfloat16*)p_hsh, (const __nv_bfloat16*)p_hsl,
        (const __nv_bfloat16*)p_Sdh, (const __nv_bfloat16*)p_Sdl,
        (float*)p_ys, MSS, 1, 0LL, HH, TT);

    // 9) combine
    combine_kernel<<<TT, 256>>>((const float*)p_ob, (const float*)p_ys,
                                (const float*)p_tw, y);
}

// round 5
// speedup vs baseline: 1.0303x; 1.0303x over previous
#include <cuda_runtime.h>
#include <cuda_bf16.h>
#include <math.h>
#include <stdint.h>

// ---------------- problem constants ----------------
#define TT   4096
#define HH   2048
#define EE   64
#define MM   1408
#define MSS  2816
#define KK   6
#define CC   768
#define NGG  8
#define TGG  3
#define NPAIR (TT*KK)        // 24576

// ---------------- device scratch ----------------
__device__ int   g_topk_i[NPAIR];
__device__ float g_topk_w[NPAIR];
__device__ int   g_cnt[EE];
__device__ int   g_lists[EE*CC];
__device__ float g_gbuf[(size_t)NPAIR*MM];   // 138 MB
__device__ float g_ubuf[(size_t)NPAIR*MM];   // 138 MB
__device__ float g_hbuf[(size_t)NPAIR*MM];   // 138 MB
__device__ float g_outb[(size_t)NPAIR*HH];   // 201 MB
__device__ float g_gs[(size_t)TT*MSS];
__device__ float g_us[(size_t)TT*MSS];
__device__ float g_hs[(size_t)TT*MSS];
__device__ float g_ys[(size_t)TT*HH];

// ---------------- gate ----------------
__global__ void gate_kernel(const float* __restrict__ x,
                            const float* __restrict__ gw,
                            int* __restrict__ ti, float* __restrict__ tw)
{
    int t = blockIdx.x;
    __shared__ float xs[HH];
    __shared__ float sc[EE];
    for (int i = threadIdx.x; i < HH; i += 64) xs[i] = x[(size_t)t*HH + i];
    __syncthreads();
    {
        int e = threadIdx.x;
        const float* w = gw + (size_t)e * HH;
        float acc = 0.f;
        #pragma unroll 8
        for (int h = 0; h < HH; ++h) acc = fmaf(xs[h], w[h], acc);
        sc[e] = acc;
    }
    __syncthreads();
    if (threadIdx.x == 0) {
        float mx = sc[0];
        for (int e = 1; e < EE; ++e) mx = fmaxf(mx, sc[e]);
        float sum = 0.f;
        for (int e = 0; e < EE; ++e) { float v = expf(sc[e] - mx); sc[e] = v; sum += v; }
        float inv = 1.f / sum;
        for (int e = 0; e < EE; ++e) sc[e] *= inv;
        float gs[NGG];
        for (int g = 0; g < NGG; ++g) {
            float m = sc[g*8];
            for (int j = 1; j < 8; ++j) m = fmaxf(m, sc[g*8 + j]);
            gs[g] = m;
        }
        unsigned gsel = 0;
        for (int it = 0; it < TGG; ++it) {
            int best = -1; float bv = -1e30f;
            for (int g = 0; g < NGG; ++g)
                if (!((gsel >> g) & 1u) && gs[g] > bv) { bv = gs[g]; best = g; }
            gsel |= 1u << best;
        }
        unsigned long long used = 0ull;
        for (int kk = 0; kk < KK; ++kk) {
            int best = -1; float bv = -1e30f;
            for (int e = 0; e < EE; ++e) {
                if (!((gsel >> (e >> 3)) & 1u)) continue;
                if ((used >> e) & 1ull) continue;
                if (sc[e] > bv) { bv = sc[e]; best = e; }
            }
            used |= 1ull << best;
            ti[t*KK + kk] = best;
            tw[t*KK + kk] = sc[best];
        }
    }
}

__global__ void zero_cnt_kernel() { if (threadIdx.x < EE) g_cnt[threadIdx.x] = 0; }

__global__ void dispatch_kernel(const int* __restrict__ ti)
{
    int p = blockIdx.x * blockDim.x + threadIdx.x;
    if (p >= NPAIR) return;
    int e = ti[p];
    int r = atomicAdd(&g_cnt[e], 1);
    if (r < CC) g_lists[e*CC + r] = p;
}

// ---------------- swiglu (fp32 out) ----------------
__global__ void swiglu_kernel(const float* __restrict__ g,
                              const float* __restrict__ u,
                              float* __restrict__ h, size_t n4)
{
    size_t i = (size_t)blockIdx.x * blockDim.x + threadIdx.x;
    size_t stride = (size_t)gridDim.x * blockDim.x;
    for (; i < n4; i += stride) {
        float4 gv = ((const float4*)g)[i];
        float4 uv = ((const float4*)u)[i];
        float4 r;
        r.x = (gv.x / (1.f + expf(-gv.x))) * uv.x;
        r.y = (gv.y / (1.f + expf(-gv.y))) * uv.y;
        r.z = (gv.z / (1.f + expf(-gv.z))) * uv.z;
        r.w = (gv.w / (1.f + expf(-gv.w))) * uv.w;
        ((float4*)h)[i] = r;
    }
}

// ======================= split-MMA GEMM with fused fp32->bf16 hi/lo =========
// Out[m,n] = sum_k A[row(m),k] * B[e][n,k], fp32 inputs, 3-pass bf16 split.
// CTA 128x128, k-chunk 32, 512 threads (16 warps of 32x32), 2-stage smem.

#define LDSM4(R, addr) asm volatile( \
    "ldmatrix.sync.aligned.m8n8.x4.shared.b16 {%0,%1,%2,%3},[%4];" \
    : "=r"((R)[0]), "=r"((R)[1]), "=r"((R)[2]), "=r"((R)[3]) : "r"(addr))
#define LDSM2(R, addr) asm volatile( \
    "ldmatrix.sync.aligned.m8n8.x2.shared.b16 {%0,%1},[%2];" \
    : "=r"((R)[0]), "=r"((R)[1]) : "r"(addr))
#define MMA16816(C, A, B) asm volatile( \
    "mma.sync.aligned.m16n8k16.row.col.f32.bf16.bf16.f32 " \
    "{%0,%1,%2,%3},{%4,%5,%6,%7},{%8,%9},{%0,%1,%2,%3};" \
    : "+f"((C)[0]), "+f"((C)[1]), "+f"((C)[2]), "+f"((C)[3]) \
    : "r"((A)[0]), "r"((A)[1]), "r"((A)[2]), "r"((A)[3]), "r"((B)[0]), "r"((B)[1]))

#define STAGE_B 40960     // 4 arrays * 128 rows * 80B
#define SMEM_TOT (2*STAGE_B + 1024)

__device__ __forceinline__ uint32_t b2u(__nv_bfloat162 v){
    return *(uint32_t*)&v;
}
__device__ __forceinline__ void cvt8(float4 A, float4 B, uint4& hi, uint4& lo){
    __nv_bfloat162 h0 = __floats2bfloat162_rn(A.x, A.y);
    __nv_bfloat162 h1 = __floats2bfloat162_rn(A.z, A.w);
    __nv_bfloat162 h2 = __floats2bfloat162_rn(B.x, B.y);
    __nv_bfloat162 h3 = __floats2bfloat162_rn(B.z, B.w);
    hi = make_uint4(b2u(h0), b2u(h1), b2u(h2), b2u(h3));
    __nv_bfloat162 l0 = __floats2bfloat162_rn(A.x - __low2float(h0), A.y - __high2float(h0));
    __nv_bfloat162 l1 = __floats2bfloat162_rn(A.z - __low2float(h1), A.w - __high2float(h1));
    __nv_bfloat162 l2 = __floats2bfloat162_rn(B.x - __low2float(h2), B.y - __high2float(h2));
    __nv_bfloat162 l3 = __floats2bfloat162_rn(B.z - __low2float(h3), B.w - __high2float(h3));
    lo = make_uint4(b2u(l0), b2u(l1), b2u(l2), b2u(l3));
}

template<bool GATHER>
__global__ void __launch_bounds__(512, 1)
fg_gemm(const float* __restrict__ A,
        const float* __restrict__ Bg,
        float* __restrict__ Out,
        int Kd, int adiv, long long bstride, int ldo, int nrows_fixed)
{
    extern __shared__ char smem[];
    const int e = blockIdx.z;
    int nrows; const int* mylist = nullptr;
    if (GATHER){ nrows = min(g_cnt[e], CC); mylist = &g_lists[e*CC]; }
    else nrows = nrows_fixed;
    const int m0 = blockIdx.y*128;
    if (m0 >= nrows) return;
    const int n0 = blockIdx.x*128;
    const float* B = Bg + (size_t)e*bstride;

    int* rowA = (int*)(smem + 2*STAGE_B);
    int* rowO = (int*)(smem + 2*STAGE_B + 512);
    const int tid = threadIdx.x;
    if (tid < 128){
        int r = m0 + tid;
        if (r < nrows){
            if (GATHER){ int p = mylist[r]; rowA[tid] = p/adiv; rowO[tid] = p; }
            else       { rowA[tid] = r;      rowO[tid] = r; }
        } else { rowA[tid] = -1; rowO[tid] = -1; }
    }
    __syncthreads();

    // loader: thread -> (row = tid>>2, chunk = tid&3) for both A and B
    const int lrow = tid >> 2, lchk = tid & 3;
    int ra = rowA[lrow]; if (ra < 0) ra = 0;
    const float* pa = A + (size_t)ra*Kd + lchk*8;
    const float* pb = B + (size_t)(n0 + lrow)*Kd + lchk*8;
    char* sdst = smem + lrow*80 + lchk*16;

    float4 a0, a1, b0, b1;
    auto ldg = [&](int kt){
        const int k0 = kt*32;
        a0 = *(const float4*)(pa + k0);
        a1 = *(const float4*)(pa + k0 + 4);
        b0 = *(const float4*)(pb + k0);
        b1 = *(const float4*)(pb + k0 + 4);
    };
    auto cvt_sts = [&](int buf){
        uint4 hi, lo;
        char* d = sdst + buf*STAGE_B;
        cvt8(a0, a1, hi, lo);
        *(uint4*)(d)         = hi;
        *(uint4*)(d + 10240) = lo;
        cvt8(b0, b1, hi, lo);
        *(uint4*)(d + 20480) = hi;
        *(uint4*)(d + 30720) = lo;
    };

    const int lane = tid & 31;
    const int wid  = tid >> 5;
    const int wm = (wid & 3) * 32;
    const int wn = (wid >> 2) * 32;

    float acc[2][4][4];
    #pragma unroll
    for (int i = 0; i < 2; ++i)
        #pragma unroll
        for (int j = 0; j < 4; ++j)
            #pragma unroll
            for (int c = 0; c < 4; ++c) acc[i][j][c] = 0.f;

    const uint32_t smem_u = (uint32_t)__cvta_generic_to_shared(smem);
    const uint32_t aoff = (uint32_t)((wm + (lane & 7) + ((lane >> 3) & 1) * 8) * 80
                                     + (lane >> 4) * 16);
    const uint32_t boff = (uint32_t)((wn + (lane & 7)) * 80 + ((lane >> 3) & 1) * 16);

    const int KT = Kd / 32;
    ldg(0);
    cvt_sts(0);
    if (KT > 1) ldg(1);

    for (int kt = 0; kt < KT; ++kt){
        __syncthreads();
        if (kt + 1 < KT) cvt_sts((kt + 1) & 1);
        if (kt + 2 < KT) ldg(kt + 2);

        const uint32_t b = smem_u + (kt & 1) * STAGE_B;
        #pragma unroll
        for (int kk = 0; kk < 2; ++kk){
            const uint32_t kb = kk * 32;
            uint32_t ah[2][4], al[2][4], bh[4][2], bl[4][2];
            #pragma unroll
            for (int mi = 0; mi < 2; ++mi){
                LDSM4(ah[mi], b + aoff + kb + mi * (16*80));
                LDSM4(al[mi], b + 10240 + aoff + kb + mi * (16*80));
            }
            #pragma unroll
            for (int ni = 0; ni < 4; ++ni){
                LDSM2(bh[ni], b + 20480 + boff + kb + ni * (8*80));
                LDSM2(bl[ni], b + 30720 + boff + kb + ni * (8*80));
            }
            #pragma unroll
            for (int mi = 0; mi < 2; ++mi)
                #pragma unroll
                for (int ni = 0; ni < 4; ++ni){
                    MMA16816(acc[mi][ni], ah[mi], bh[ni]);
                    MMA16816(acc[mi][ni], ah[mi], bl[ni]);
                    MMA16816(acc[mi][ni], al[mi], bh[ni]);
                }
        }
    }

    // epilogue
    const int g4 = lane >> 2, tig = lane & 3;
    #pragma unroll
    for (int mi = 0; mi < 2; ++mi){
        int r0 = wm + mi*16 + g4;
        int r1 = r0 + 8;
        int o0 = rowO[r0], o1 = rowO[r1];
        #pragma unroll
        for (int ni = 0; ni < 4; ++ni){
            int cc = n0 + wn + ni*8 + tig*2;
            if (o0 >= 0)
                *(float2*)(Out + (size_t)o0*ldo + cc) = make_float2(acc[mi][ni][0], acc[mi][ni][1]);
            if (o1 >= 0)
                *(float2*)(Out + (size_t)o1*ldo + cc) = make_float2(acc[mi][ni][2], acc[mi][ni][3]);
        }
    }
}

// ---------------- combine ----------------
__global__ void combine_kernel(const float* __restrict__ ob,
                               const float* __restrict__ ys,
                               const float* __restrict__ tw,
                               float* __restrict__ y)
{
    int t = blockIdx.x;
    for (int c = threadIdx.x; c < HH; c += blockDim.x) {
        float acc = ys[(size_t)t*HH + c];
        #pragma unroll
        for (int k = 0; k < KK; ++k) {
            int p = t*KK + k;
            acc = fmaf(tw[p], ob[(size_t)p*HH + c], acc);
        }
        y[(size_t)t*HH + c] = acc;
    }
}

// ---------------- launch ----------------
extern "C" void kernel_launch(void* const* d_in, const int* in_sizes, int n_in,
                              void* d_out, int out_size)
{
    const float* x  = (const float*)d_in[0];
    const float* gw = (const float*)d_in[1];
    const float* Wg = (const float*)d_in[2];
    const float* Wu = (const float*)d_in[3];
    const float* Wd = (const float*)d_in[4];
    const float* Sg = (const float*)d_in[5];
    const float* Su = (const float*)d_in[6];
    const float* Sd = (const float*)d_in[7];
    float* y = (float*)d_out;

    void *p_ti, *p_tw, *p_g, *p_u, *p_h, *p_ob, *p_gs, *p_us, *p_hs, *p_ys;
    cudaGetSymbolAddress(&p_ti, g_topk_i);  cudaGetSymbolAddress(&p_tw, g_topk_w);
    cudaGetSymbolAddress(&p_g,  g_gbuf);    cudaGetSymbolAddress(&p_u,  g_ubuf);
    cudaGetSymbolAddress(&p_h,  g_hbuf);    cudaGetSymbolAddress(&p_ob, g_outb);
    cudaGetSymbolAddress(&p_gs, g_gs);      cudaGetSymbolAddress(&p_us, g_us);
    cudaGetSymbolAddress(&p_hs, g_hs);      cudaGetSymbolAddress(&p_ys, g_ys);

    cudaFuncSetAttribute(fg_gemm<true>,  cudaFuncAttributeMaxDynamicSharedMemorySize, SMEM_TOT);
    cudaFuncSetAttribute(fg_gemm<false>, cudaFuncAttributeMaxDynamicSharedMemorySize, SMEM_TOT);

    // 1) gate + dispatch
    gate_kernel<<<TT, 64>>>(x, gw, (int*)p_ti, (float*)p_tw);
    zero_cnt_kernel<<<1, 64>>>();
    dispatch_kernel<<<(NPAIR + 255)/256, 256>>>((const int*)p_ti);

    // 2) routed GEMM1: g and u (A = gathered x rows fp32, K = HH)
    fg_gemm<true><<<dim3(MM/128, CC/128, EE), 512, SMEM_TOT>>>(
        x, Wg, (float*)p_g, HH, KK, (long long)MM*HH, MM, 0);
    fg_gemm<true><<<dim3(MM/128, CC/128, EE), 512, SMEM_TOT>>>(
        x, Wu, (float*)p_u, HH, KK, (long long)MM*HH, MM, 0);

    // 3) swiglu -> h (fp32)
    {
        size_t n4 = (size_t)NPAIR*MM/4;
        swiglu_kernel<<<(int)((n4 + 255)/256), 256>>>((const float*)p_g, (const float*)p_u,
                                                      (float*)p_h, n4);
    }

    // 4) routed GEMM2 (Wd): A = h rows by pair id, K = MM
    fg_gemm<true><<<dim3(HH/128, CC/128, EE), 512, SMEM_TOT>>>(
        (const float*)p_h, Wd, (float*)p_ob, MM, 1, (long long)HH*MM, HH, 0);

    // 5) shared expert g,u (K = HH)
    fg_gemm<false><<<dim3(MSS/128, TT/128, 1), 512, SMEM_TOT>>>(
        x, Sg, (float*)p_gs, HH, 1, 0LL, MSS, TT);
    fg_gemm<false><<<dim3(MSS/128, TT/128, 1), 512, SMEM_TOT>>>(
        x, Su, (float*)p_us, HH, 1, 0LL, MSS, TT);

    // 6) shared swiglu
    {
        size_t n4 = (size_t)TT*MSS/4;
        swiglu_kernel<<<(int)((n4 + 255)/256), 256>>>((const float*)p_gs, (const float*)p_us,
                                                      (float*)p_hs, n4);
    }

    // 7) shared GEMM2 (Sd, K = MSS)
    fg_gemm<false><<<dim3(HH/128, TT/128, 1), 512, SMEM_TOT>>>(
        (const float*)p_hs, Sd, (float*)p_ys, MSS, 1, 0LL, HH, TT);

    // 8) combine
    combine_kernel<<<TT, 256>>>((const float*)p_ob, (const float*)p_ys,
                                (const float*)p_tw, y);
}

// round 6
// speedup vs baseline: 1.0331x; 1.0028x over previous
#include <cuda_runtime.h>
#include <cuda_bf16.h>
#include <math.h>
#include <stdint.h>

// ---------------- problem constants ----------------
#define TT   4096
#define HH   2048
#define EE   64
#define MM   1408
#define MSS  2816
#define KK   6
#define CC   768
#define NGG  8
#define TGG  3
#define NPAIR (TT*KK)        // 24576

// ---------------- device scratch ----------------
__device__ int   g_topk_i[NPAIR];
__device__ float g_topk_w[NPAIR];
__device__ int   g_cnt[EE];
__device__ int   g_lists[EE*CC];
__device__ float g_gbuf[(size_t)NPAIR*MM];
__device__ float g_ubuf[(size_t)NPAIR*MM];
__device__ float g_hbuf[(size_t)NPAIR*MM];
__device__ float g_outb[(size_t)NPAIR*HH];
__device__ float g_gs[(size_t)TT*MSS];
__device__ float g_us[(size_t)TT*MSS];
__device__ float g_hs[(size_t)TT*MSS];
__device__ float g_ys[(size_t)TT*HH];

// ---------------- gate ----------------
__global__ void gate_kernel(const float* __restrict__ x,
                            const float* __restrict__ gw,
                            int* __restrict__ ti, float* __restrict__ tw)
{
    int t = blockIdx.x;
    __shared__ float xs[HH];
    __shared__ float sc[EE];
    for (int i = threadIdx.x; i < HH; i += 64) xs[i] = x[(size_t)t*HH + i];
    __syncthreads();
    {
        int e = threadIdx.x;
        const float* w = gw + (size_t)e * HH;
        float acc = 0.f;
        #pragma unroll 8
        for (int h = 0; h < HH; ++h) acc = fmaf(xs[h], w[h], acc);
        sc[e] = acc;
    }
    __syncthreads();
    if (threadIdx.x == 0) {
        float mx = sc[0];
        for (int e = 1; e < EE; ++e) mx = fmaxf(mx, sc[e]);
        float sum = 0.f;
        for (int e = 0; e < EE; ++e) { float v = expf(sc[e] - mx); sc[e] = v; sum += v; }
        float inv = 1.f / sum;
        for (int e = 0; e < EE; ++e) sc[e] *= inv;
        float gs[NGG];
        for (int g = 0; g < NGG; ++g) {
            float m = sc[g*8];
            for (int j = 1; j < 8; ++j) m = fmaxf(m, sc[g*8 + j]);
            gs[g] = m;
        }
        unsigned gsel = 0;
        for (int it = 0; it < TGG; ++it) {
            int best = -1; float bv = -1e30f;
            for (int g = 0; g < NGG; ++g)
                if (!((gsel >> g) & 1u) && gs[g] > bv) { bv = gs[g]; best = g; }
            gsel |= 1u << best;
        }
        unsigned long long used = 0ull;
        for (int kk = 0; kk < KK; ++kk) {
            int best = -1; float bv = -1e30f;
            for (int e = 0; e < EE; ++e) {
                if (!((gsel >> (e >> 3)) & 1u)) continue;
                if ((used >> e) & 1ull) continue;
                if (sc[e] > bv) { bv = sc[e]; best = e; }
            }
            used |= 1ull << best;
            ti[t*KK + kk] = best;
            tw[t*KK + kk] = sc[best];
        }
    }
}

__global__ void zero_cnt_kernel() { if (threadIdx.x < EE) g_cnt[threadIdx.x] = 0; }

__global__ void dispatch_kernel(const int* __restrict__ ti)
{
    int p = blockIdx.x * blockDim.x + threadIdx.x;
    if (p >= NPAIR) return;
    int e = ti[p];
    int r = atomicAdd(&g_cnt[e], 1);
    if (r < CC) g_lists[e*CC + r] = p;
}

// ---------------- swiglu (fp32 out) ----------------
__global__ void swiglu_kernel(const float* __restrict__ g,
                              const float* __restrict__ u,
                              float* __restrict__ h, size_t n4)
{
    size_t i = (size_t)blockIdx.x * blockDim.x + threadIdx.x;
    size_t stride = (size_t)gridDim.x * blockDim.x;
    for (; i < n4; i += stride) {
        float4 gv = ((const float4*)g)[i];
        float4 uv = ((const float4*)u)[i];
        float4 r;
        r.x = (gv.x / (1.f + expf(-gv.x))) * uv.x;
        r.y = (gv.y / (1.f + expf(-gv.y))) * uv.y;
        r.z = (gv.z / (1.f + expf(-gv.z))) * uv.z;
        r.w = (gv.w / (1.f + expf(-gv.w))) * uv.w;
        ((float4*)h)[i] = r;
    }
}

// ======================= split-MMA GEMM, fused fp32->bf16 hi/lo =========
// CTA 128x64, k-chunk 32, 256 threads (8 warps of 32x32), 2-stage smem,
// 2 CTAs/SM for cross-CTA barrier overlap.

#define LDSM4(R, addr) asm volatile( \
    "ldmatrix.sync.aligned.m8n8.x4.shared.b16 {%0,%1,%2,%3},[%4];" \
    : "=r"((R)[0]), "=r"((R)[1]), "=r"((R)[2]), "=r"((R)[3]) : "r"(addr))
#define LDSM2(R, addr) asm volatile( \
    "ldmatrix.sync.aligned.m8n8.x2.shared.b16 {%0,%1},[%2];" \
    : "=r"((R)[0]), "=r"((R)[1]) : "r"(addr))
#define MMA16816(C, A, B) asm volatile( \
    "mma.sync.aligned.m16n8k16.row.col.f32.bf16.bf16.f32 " \
    "{%0,%1,%2,%3},{%4,%5,%6,%7},{%8,%9},{%0,%1,%2,%3};" \
    : "+f"((C)[0]), "+f"((C)[1]), "+f"((C)[2]), "+f"((C)[3]) \
    : "r"((A)[0]), "r"((A)[1]), "r"((A)[2]), "r"((A)[3]), "r"((B)[0]), "r"((B)[1]))

// stage layout (bytes): Ahi 0 (128*80), Alo 10240, Bhi 20480 (64*80), Blo 25600
#define STAGE_B 30720
#define SMEM_TOT (2*STAGE_B + 1024)

__device__ __forceinline__ uint32_t b2u(__nv_bfloat162 v){ return *(uint32_t*)&v; }
__device__ __forceinline__ void cvt8(float4 A, float4 B, uint4& hi, uint4& lo){
    __nv_bfloat162 h0 = __floats2bfloat162_rn(A.x, A.y);
    __nv_bfloat162 h1 = __floats2bfloat162_rn(A.z, A.w);
    __nv_bfloat162 h2 = __floats2bfloat162_rn(B.x, B.y);
    __nv_bfloat162 h3 = __floats2bfloat162_rn(B.z, B.w);
    hi = make_uint4(b2u(h0), b2u(h1), b2u(h2), b2u(h3));
    __nv_bfloat162 l0 = __floats2bfloat162_rn(A.x - __low2float(h0), A.y - __high2float(h0));
    __nv_bfloat162 l1 = __floats2bfloat162_rn(A.z - __low2float(h1), A.w - __high2float(h1));
    __nv_bfloat162 l2 = __floats2bfloat162_rn(B.x - __low2float(h2), B.y - __high2float(h2));
    __nv_bfloat162 l3 = __floats2bfloat162_rn(B.z - __low2float(h3), B.w - __high2float(h3));
    lo = make_uint4(b2u(l0), b2u(l1), b2u(l2), b2u(l3));
}

template<bool GATHER>
__global__ void __launch_bounds__(256, 2)
fg_gemm(const float* __restrict__ A,
        const float* __restrict__ Bg,
        float* __restrict__ Out,
        int Kd, int adiv, long long bstride, int ldo, int nrows_fixed)
{
    extern __shared__ char smem[];
    const int e = blockIdx.z;
    int nrows; const int* mylist = nullptr;
    if (GATHER){ nrows = min(g_cnt[e], CC); mylist = &g_lists[e*CC]; }
    else nrows = nrows_fixed;
    const int m0 = blockIdx.y*128;
    if (m0 >= nrows) return;
    const int n0 = blockIdx.x*64;
    const float* B = Bg + (size_t)e*bstride;

    int* rowA = (int*)(smem + 2*STAGE_B);
    int* rowO = (int*)(smem + 2*STAGE_B + 512);
    const int tid = threadIdx.x;
    if (tid < 128){
        int r = m0 + tid;
        if (r < nrows){
            if (GATHER){ int p = mylist[r]; rowA[tid] = p/adiv; rowO[tid] = p; }
            else       { rowA[tid] = r;      rowO[tid] = r; }
        } else { rowA[tid] = -1; rowO[tid] = -1; }
    }
    __syncthreads();

    // A loader: thread -> row = tid>>1 (0..127), half = tid&1 (16 floats)
    // B loader: thread -> row = tid>>2 (0..63), quarter = tid&3 (8 floats)
    const int arow_l = tid >> 1, ahalf = tid & 1;
    const int brow_l = tid >> 2, bq = tid & 3;
    int ra = rowA[arow_l]; if (ra < 0) ra = 0;
    const float* pa = A + (size_t)ra*Kd + ahalf*16;
    const float* pb = B + (size_t)(n0 + brow_l)*Kd + bq*8;
    char* sa = smem + arow_l*80 + ahalf*32;
    char* sb = smem + 20480 + brow_l*80 + bq*16;

    float4 a0, a1, a2, a3, b0, b1;
    auto ldg = [&](int kt){
        const int k0 = kt*32;
        a0 = *(const float4*)(pa + k0);
        a1 = *(const float4*)(pa + k0 + 4);
        a2 = *(const float4*)(pa + k0 + 8);
        a3 = *(const float4*)(pa + k0 + 12);
        b0 = *(const float4*)(pb + k0);
        b1 = *(const float4*)(pb + k0 + 4);
    };
    auto cvt_sts = [&](int buf){
        uint4 hi, lo;
        char* da = sa + buf*STAGE_B;
        char* db = sb + buf*STAGE_B;
        cvt8(a0, a1, hi, lo);
        *(uint4*)(da)             = hi;
        *(uint4*)(da + 10240)     = lo;
        cvt8(a2, a3, hi, lo);
        *(uint4*)(da + 16)        = hi;
        *(uint4*)(da + 10240+16)  = lo;
        cvt8(b0, b1, hi, lo);
        *(uint4*)(db)             = hi;
        *(uint4*)(db + 5120)      = lo;
    };

    const int lane = tid & 31;
    const int wid  = tid >> 5;
    const int wm = (wid & 3) * 32;
    const int wn = (wid >> 2) * 32;

    float acc[2][4][4];
    #pragma unroll
    for (int i = 0; i < 2; ++i)
        #pragma unroll
        for (int j = 0; j < 4; ++j)
            #pragma unroll
            for (int c = 0; c < 4; ++c) acc[i][j][c] = 0.f;

    const uint32_t smem_u = (uint32_t)__cvta_generic_to_shared(smem);
    const uint32_t aoff = (uint32_t)((wm + (lane & 7) + ((lane >> 3) & 1) * 8) * 80
                                     + (lane >> 4) * 16);
    const uint32_t boff = (uint32_t)(20480 + (wn + (lane & 7)) * 80 + ((lane >> 3) & 1) * 16);

    const int KT = Kd / 32;
    ldg(0);
    cvt_sts(0);
    if (KT > 1) ldg(1);

    for (int kt = 0; kt < KT; ++kt){
        __syncthreads();
        if (kt + 1 < KT) cvt_sts((kt + 1) & 1);
        if (kt + 2 < KT) ldg(kt + 2);

        const uint32_t b = smem_u + (kt & 1) * STAGE_B;
        #pragma unroll
        for (int kk = 0; kk < 2; ++kk){
            const uint32_t kb = kk * 32;
            uint32_t ah[2][4], al[2][4], bh[4][2], bl[4][2];
            #pragma unroll
            for (int mi = 0; mi < 2; ++mi){
                LDSM4(ah[mi], b + aoff + kb + mi * (16*80));
                LDSM4(al[mi], b + 10240 + aoff + kb + mi * (16*80));
            }
            #pragma unroll
            for (int ni = 0; ni < 4; ++ni){
                LDSM2(bh[ni], b + boff + kb + ni * (8*80));
                LDSM2(bl[ni], b + 5120 + boff + kb + ni * (8*80));
            }
            #pragma unroll
            for (int mi = 0; mi < 2; ++mi)
                #pragma unroll
                for (int ni = 0; ni < 4; ++ni){
                    MMA16816(acc[mi][ni], ah[mi], bh[ni]);
                    MMA16816(acc[mi][ni], ah[mi], bl[ni]);
                    MMA16816(acc[mi][ni], al[mi], bh[ni]);
                }
        }
    }

    // epilogue
    const int g4 = lane >> 2, tig = lane & 3;
    #pragma unroll
    for (int mi = 0; mi < 2; ++mi){
        int r0 = wm + mi*16 + g4;
        int r1 = r0 + 8;
        int o0 = rowO[r0], o1 = rowO[r1];
        #pragma unroll
        for (int ni = 0; ni < 4; ++ni){
            int cc = n0 + wn + ni*8 + tig*2;
            if (o0 >= 0)
                *(float2*)(Out + (size_t)o0*ldo + cc) = make_float2(acc[mi][ni][0], acc[mi][ni][1]);
            if (o1 >= 0)
                *(float2*)(Out + (size_t)o1*ldo + cc) = make_float2(acc[mi][ni][2], acc[mi][ni][3]);
        }
    }
}

// ---------------- combine ----------------
__global__ void combine_kernel(const float* __restrict__ ob,
                               const float* __restrict__ ys,
                               const float* __restrict__ tw,
                               float* __restrict__ y)
{
    int t = blockIdx.x;
    for (int c = threadIdx.x; c < HH; c += blockDim.x) {
        float acc = ys[(size_t)t*HH + c];
        #pragma unroll
        for (int k = 0; k < KK; ++k) {
            int p = t*KK + k;
            acc = fmaf(tw[p], ob[(size_t)p*HH + c], acc);
        }
        y[(size_t)t*HH + c] = acc;
    }
}

// ---------------- launch ----------------
extern "C" void kernel_launch(void* const* d_in, const int* in_sizes, int n_in,
                              void* d_out, int out_size)
{
    const float* x  = (const float*)d_in[0];
    const float* gw = (const float*)d_in[1];
    const float* Wg = (const float*)d_in[2];
    const float* Wu = (const float*)d_in[3];
    const float* Wd = (const float*)d_in[4];
    const float* Sg = (const float*)d_in[5];
    const float* Su = (const float*)d_in[6];
    const float* Sd = (const float*)d_in[7];
    float* y = (float*)d_out;

    void *p_ti, *p_tw, *p_g, *p_u, *p_h, *p_ob, *p_gs, *p_us, *p_hs, *p_ys;
    cudaGetSymbolAddress(&p_ti, g_topk_i);  cudaGetSymbolAddress(&p_tw, g_topk_w);
    cudaGetSymbolAddress(&p_g,  g_gbuf);    cudaGetSymbolAddress(&p_u,  g_ubuf);
    cudaGetSymbolAddress(&p_h,  g_hbuf);    cudaGetSymbolAddress(&p_ob, g_outb);
    cudaGetSymbolAddress(&p_gs, g_gs);      cudaGetSymbolAddress(&p_us, g_us);
    cudaGetSymbolAddress(&p_hs, g_hs);      cudaGetSymbolAddress(&p_ys, g_ys);

    cudaFuncSetAttribute(fg_gemm<true>,  cudaFuncAttributeMaxDynamicSharedMemorySize, SMEM_TOT);
    cudaFuncSetAttribute(fg_gemm<false>, cudaFuncAttributeMaxDynamicSharedMemorySize, SMEM_TOT);

    // 1) gate + dispatch
    gate_kernel<<<TT, 64>>>(x, gw, (int*)p_ti, (float*)p_tw);
    zero_cnt_kernel<<<1, 64>>>();
    dispatch_kernel<<<(NPAIR + 255)/256, 256>>>((const int*)p_ti);

    // 2) routed GEMM1: g and u (A = gathered x rows fp32, K = HH)
    fg_gemm<true><<<dim3(MM/64, CC/128, EE), 256, SMEM_TOT>>>(
        x, Wg, (float*)p_g, HH, KK, (long long)MM*HH, MM, 0);
    fg_gemm<true><<<dim3(MM/64, CC/128, EE), 256, SMEM_TOT>>>(
        x, Wu, (float*)p_u, HH, KK, (long long)MM*HH, MM, 0);

    // 3) swiglu -> h (fp32)
    {
        size_t n4 = (size_t)NPAIR*MM/4;
        swiglu_kernel<<<(int)((n4 + 255)/256), 256>>>((const float*)p_g, (const float*)p_u,
                                                      (float*)p_h, n4);
    }

    // 4) routed GEMM2 (Wd): A = h rows by pair id, K = MM
    fg_gemm<true><<<dim3(HH/64, CC/128, EE), 256, SMEM_TOT>>>(
        (const float*)p_h, Wd, (float*)p_ob, MM, 1, (long long)HH*MM, HH, 0);

    // 5) shared expert g,u (K = HH)
    fg_gemm<false><<<dim3(MSS/64, TT/128, 1), 256, SMEM_TOT>>>(
        x, Sg, (float*)p_gs, HH, 1, 0LL, MSS, TT);
    fg_gemm<false><<<dim3(MSS/64, TT/128, 1), 256, SMEM_TOT>>>(
        x, Su, (float*)p_us, HH, 1, 0LL, MSS, TT);

    // 6) shared swiglu
    {
        size_t n4 = (size_t)TT*MSS/4;
        swiglu_kernel<<<(int)((n4 + 255)/256), 256>>>((const float*)p_gs, (const float*)p_us,
                                                      (float*)p_hs, n4);
    }

    // 7) shared GEMM2 (Sd, K = MSS)
    fg_gemm<false><<<dim3(HH/64, TT/128, 1), 256, SMEM_TOT>>>(
        (const float*)p_hs, Sd, (float*)p_ys, MSS, 1, 0LL, HH, TT);

    // 8) combine
    combine_kernel<<<TT, 256>>>((const float*)p_ob, (const float*)p_ys,
                                (const float*)p_tw, y);
}

// round 7
// speedup vs baseline: 1.1275x; 1.0914x over previous
#include <cuda_runtime.h>
#include <cuda_bf16.h>
#include <math.h>
#include <stdint.h>

// ---------------- problem constants ----------------
#define TT   4096
#define HH   2048
#define EE   64
#define MM   1408
#define MSS  2816
#define KK   6
#define CC   768
#define NGG  8
#define TGG  3
#define NPAIR (TT*KK)        // 24576

// ---------------- device scratch ----------------
__device__ int   g_topk_i[NPAIR];
__device__ float g_topk_w[NPAIR];
__device__ int   g_cnt[EE];
__device__ int   g_lists[EE*CC];
__device__ float g_gbuf[(size_t)NPAIR*MM];
__device__ float g_ubuf[(size_t)NPAIR*MM];
__device__ float g_hbuf[(size_t)NPAIR*MM];
__device__ float g_outb[(size_t)NPAIR*HH];
__device__ float g_gs[(size_t)TT*MSS];
__device__ float g_us[(size_t)TT*MSS];
__device__ float g_hs[(size_t)TT*MSS];
__device__ float g_ys[(size_t)TT*HH];

// ---------------- gate ----------------
__global__ void gate_kernel(const float* __restrict__ x,
                            const float* __restrict__ gw,
                            int* __restrict__ ti, float* __restrict__ tw)
{
    int t = blockIdx.x;
    __shared__ float xs[HH];
    __shared__ float sc[EE];
    for (int i = threadIdx.x; i < HH; i += 64) xs[i] = x[(size_t)t*HH + i];
    __syncthreads();
    {
        int e = threadIdx.x;
        const float* w = gw + (size_t)e * HH;
        float acc = 0.f;
        #pragma unroll 8
        for (int h = 0; h < HH; ++h) acc = fmaf(xs[h], w[h], acc);
        sc[e] = acc;
    }
    __syncthreads();
    if (threadIdx.x == 0) {
        float mx = sc[0];
        for (int e = 1; e < EE; ++e) mx = fmaxf(mx, sc[e]);
        float sum = 0.f;
        for (int e = 0; e < EE; ++e) { float v = expf(sc[e] - mx); sc[e] = v; sum += v; }
        float inv = 1.f / sum;
        for (int e = 0; e < EE; ++e) sc[e] *= inv;
        float gs[NGG];
        for (int g = 0; g < NGG; ++g) {
            float m = sc[g*8];
            for (int j = 1; j < 8; ++j) m = fmaxf(m, sc[g*8 + j]);
            gs[g] = m;
        }
        unsigned gsel = 0;
        for (int it = 0; it < TGG; ++it) {
            int best = -1; float bv = -1e30f;
            for (int g = 0; g < NGG; ++g)
                if (!((gsel >> g) & 1u) && gs[g] > bv) { bv = gs[g]; best = g; }
            gsel |= 1u << best;
        }
        unsigned long long used = 0ull;
        for (int kk = 0; kk < KK; ++kk) {
            int best = -1; float bv = -1e30f;
            for (int e = 0; e < EE; ++e) {
                if (!((gsel >> (e >> 3)) & 1u)) continue;
                if ((used >> e) & 1ull) continue;
                if (sc[e] > bv) { bv = sc[e]; best = e; }
            }
            used |= 1ull << best;
            ti[t*KK + kk] = best;
            tw[t*KK + kk] = sc[best];
        }
    }
}

__global__ void zero_cnt_kernel() { if (threadIdx.x < EE) g_cnt[threadIdx.x] = 0; }

__global__ void dispatch_kernel(const int* __restrict__ ti)
{
    int p = blockIdx.x * blockDim.x + threadIdx.x;
    if (p >= NPAIR) return;
    int e = ti[p];
    int r = atomicAdd(&g_cnt[e], 1);
    if (r < CC) g_lists[e*CC + r] = p;
}

// ---------------- swiglu (fp32 out) ----------------
__global__ void swiglu_kernel(const float* __restrict__ g,
                              const float* __restrict__ u,
                              float* __restrict__ h, size_t n4)
{
    size_t i = (size_t)blockIdx.x * blockDim.x + threadIdx.x;
    size_t stride = (size_t)gridDim.x * blockDim.x;
    for (; i < n4; i += stride) {
        float4 gv = ((const float4*)g)[i];
        float4 uv = ((const float4*)u)[i];
        float4 r;
        r.x = (gv.x / (1.f + expf(-gv.x))) * uv.x;
        r.y = (gv.y / (1.f + expf(-gv.y))) * uv.y;
        r.z = (gv.z / (1.f + expf(-gv.z))) * uv.z;
        r.w = (gv.w / (1.f + expf(-gv.w))) * uv.w;
        ((float4*)h)[i] = r;
    }
}

// ======================= split-MMA GEMM, fused fp32->bf16 hi/lo =========
// CTA 128x128, k-chunk 32, 256 threads (8 warps of 64x32), 2-stage smem.

#define LDSM4(R, addr) asm volatile( \
    "ldmatrix.sync.aligned.m8n8.x4.shared.b16 {%0,%1,%2,%3},[%4];" \
    : "=r"((R)[0]), "=r"((R)[1]), "=r"((R)[2]), "=r"((R)[3]) : "r"(addr))
#define LDSM2(R, addr) asm volatile( \
    "ldmatrix.sync.aligned.m8n8.x2.shared.b16 {%0,%1},[%2];" \
    : "=r"((R)[0]), "=r"((R)[1]) : "r"(addr))
#define MMA16816(C, A, B) asm volatile( \
    "mma.sync.aligned.m16n8k16.row.col.f32.bf16.bf16.f32 " \
    "{%0,%1,%2,%3},{%4,%5,%6,%7},{%8,%9},{%0,%1,%2,%3};" \
    : "+f"((C)[0]), "+f"((C)[1]), "+f"((C)[2]), "+f"((C)[3]) \
    : "r"((A)[0]), "r"((A)[1]), "r"((A)[2]), "r"((A)[3]), "r"((B)[0]), "r"((B)[1]))

// stage layout (bytes): Ahi 0 (128*80), Alo 10240, Bhi 20480 (128*80), Blo 30720
#define STAGE_B 40960
#define SMEM_TOT (2*STAGE_B + 1024)

__device__ __forceinline__ uint32_t b2u(__nv_bfloat162 v){ return *(uint32_t*)&v; }
__device__ __forceinline__ void cvt8(float4 A, float4 B, uint4& hi, uint4& lo){
    __nv_bfloat162 h0 = __floats2bfloat162_rn(A.x, A.y);
    __nv_bfloat162 h1 = __floats2bfloat162_rn(A.z, A.w);
    __nv_bfloat162 h2 = __floats2bfloat162_rn(B.x, B.y);
    __nv_bfloat162 h3 = __floats2bfloat162_rn(B.z, B.w);
    hi = make_uint4(b2u(h0), b2u(h1), b2u(h2), b2u(h3));
    __nv_bfloat162 l0 = __floats2bfloat162_rn(A.x - __low2float(h0), A.y - __high2float(h0));
    __nv_bfloat162 l1 = __floats2bfloat162_rn(A.z - __low2float(h1), A.w - __high2float(h1));
    __nv_bfloat162 l2 = __floats2bfloat162_rn(B.x - __low2float(h2), B.y - __high2float(h2));
    __nv_bfloat162 l3 = __floats2bfloat162_rn(B.z - __low2float(h3), B.w - __high2float(h3));
    lo = make_uint4(b2u(l0), b2u(l1), b2u(l2), b2u(l3));
}

template<bool GATHER>
__global__ void __launch_bounds__(256)
fg_gemm(const float* __restrict__ A,
        const float* __restrict__ Bg,
        float* __restrict__ Out,
        int Kd, int adiv, long long bstride, int ldo, int nrows_fixed)
{
    extern __shared__ char smem[];
    const int e = blockIdx.z;
    int nrows; const int* mylist = nullptr;
    if (GATHER){ nrows = min(g_cnt[e], CC); mylist = &g_lists[e*CC]; }
    else nrows = nrows_fixed;
    const int m0 = blockIdx.y*128;
    if (m0 >= nrows) return;
    const int n0 = blockIdx.x*128;
    const float* B = Bg + (size_t)e*bstride;

    int* rowA = (int*)(smem + 2*STAGE_B);
    int* rowO = (int*)(smem + 2*STAGE_B + 512);
    const int tid = threadIdx.x;
    if (tid < 128){
        int r = m0 + tid;
        if (r < nrows){
            if (GATHER){ int p = mylist[r]; rowA[tid] = p/adiv; rowO[tid] = p; }
            else       { rowA[tid] = r;      rowO[tid] = r; }
        } else { rowA[tid] = -1; rowO[tid] = -1; }
    }
    __syncthreads();

    // loaders: row = tid>>1 (0..127), half = tid&1 (16 floats each)
    const int lrow = tid >> 1, half = tid & 1;
    int ra = rowA[lrow]; if (ra < 0) ra = 0;
    const float* pa = A + (size_t)ra*Kd + half*16;
    const float* pb = B + (size_t)(n0 + lrow)*Kd + half*16;
    char* sa = smem + lrow*80 + half*32;
    char* sb = smem + 20480 + lrow*80 + half*32;

    float4 a0, a1, a2, a3, b0, b1, b2, b3;
    auto ldg = [&](int kt){
        const int k0 = kt*32;
        a0 = *(const float4*)(pa + k0);
        a1 = *(const float4*)(pa + k0 + 4);
        a2 = *(const float4*)(pa + k0 + 8);
        a3 = *(const float4*)(pa + k0 + 12);
        b0 = *(const float4*)(pb + k0);
        b1 = *(const float4*)(pb + k0 + 4);
        b2 = *(const float4*)(pb + k0 + 8);
        b3 = *(const float4*)(pb + k0 + 12);
    };
    auto cvt_sts = [&](int buf){
        uint4 hi, lo;
        char* da = sa + buf*STAGE_B;
        char* db = sb + buf*STAGE_B;
        cvt8(a0, a1, hi, lo);
        *(uint4*)(da)            = hi;
        *(uint4*)(da + 10240)    = lo;
        cvt8(a2, a3, hi, lo);
        *(uint4*)(da + 16)       = hi;
        *(uint4*)(da + 10256)    = lo;
        cvt8(b0, b1, hi, lo);
        *(uint4*)(db)            = hi;
        *(uint4*)(db + 10240)    = lo;
        cvt8(b2, b3, hi, lo);
        *(uint4*)(db + 16)       = hi;
        *(uint4*)(db + 10256)    = lo;
    };

    const int lane = tid & 31;
    const int wid  = tid >> 5;
    const int wm = (wid & 1) * 64;       // warp tile 64x32
    const int wn = (wid >> 1) * 32;

    float acc[4][4][4];
    #pragma unroll
    for (int i = 0; i < 4; ++i)
        #pragma unroll
        for (int j = 0; j < 4; ++j)
            #pragma unroll
            for (int c = 0; c < 4; ++c) acc[i][j][c] = 0.f;

    const uint32_t smem_u = (uint32_t)__cvta_generic_to_shared(smem);
    const uint32_t aoff = (uint32_t)((wm + (lane & 7) + ((lane >> 3) & 1) * 8) * 80
                                     + (lane >> 4) * 16);
    const uint32_t boff = (uint32_t)(20480 + (wn + (lane & 7)) * 80 + ((lane >> 3) & 1) * 16);

    const int KT = Kd / 32;
    ldg(0);
    cvt_sts(0);
    if (KT > 1) ldg(1);

    for (int kt = 0; kt < KT; ++kt){
        __syncthreads();
        if (kt + 1 < KT) cvt_sts((kt + 1) & 1);
        if (kt + 2 < KT) ldg(kt + 2);

        const uint32_t b = smem_u + (kt & 1) * STAGE_B;
        #pragma unroll
        for (int kk = 0; kk < 2; ++kk){
            const uint32_t kb = kk * 32;
            uint32_t ah[4][4], al[4][4], bh[4][2], bl[4][2];
            #pragma unroll
            for (int mi = 0; mi < 4; ++mi){
                LDSM4(ah[mi], b + aoff + kb + mi * (16*80));
                LDSM4(al[mi], b + 10240 + aoff + kb + mi * (16*80));
            }
            #pragma unroll
            for (int ni = 0; ni < 4; ++ni){
                LDSM2(bh[ni], b + boff + kb + ni * (8*80));
                LDSM2(bl[ni], b + 10240 + boff + kb + ni * (8*80));
            }
            #pragma unroll
            for (int mi = 0; mi < 4; ++mi)
                #pragma unroll
                for (int ni = 0; ni < 4; ++ni){
                    MMA16816(acc[mi][ni], ah[mi], bh[ni]);
                    MMA16816(acc[mi][ni], ah[mi], bl[ni]);
                    MMA16816(acc[mi][ni], al[mi], bh[ni]);
                }
        }
    }

    // epilogue
    const int g4 = lane >> 2, tig = lane & 3;
    #pragma unroll
    for (int mi = 0; mi < 4; ++mi){
        int r0 = wm + mi*16 + g4;
        int r1 = r0 + 8;
        int o0 = rowO[r0], o1 = rowO[r1];
        #pragma unroll
        for (int ni = 0; ni < 4; ++ni){
            int cc = n0 + wn + ni*8 + tig*2;
            if (o0 >= 0)
                *(float2*)(Out + (size_t)o0*ldo + cc) = make_float2(acc[mi][ni][0], acc[mi][ni][1]);
            if (o1 >= 0)
                *(float2*)(Out + (size_t)o1*ldo + cc) = make_float2(acc[mi][ni][2], acc[mi][ni][3]);
        }
    }
}

// ---------------- combine ----------------
__global__ void combine_kernel(const float* __restrict__ ob,
                               const float* __restrict__ ys,
                               const float* __restrict__ tw,
                               float* __restrict__ y)
{
    int t = blockIdx.x;
    for (int c = threadIdx.x; c < HH; c += blockDim.x) {
        float acc = ys[(size_t)t*HH + c];
        #pragma unroll
        for (int k = 0; k < KK; ++k) {
            int p = t*KK + k;
            acc = fmaf(tw[p], ob[(size_t)p*HH + c], acc);
        }
        y[(size_t)t*HH + c] = acc;
    }
}

// ---------------- launch ----------------
extern "C" void kernel_launch(void* const* d_in, const int* in_sizes, int n_in,
                              void* d_out, int out_size)
{
    const float* x  = (const float*)d_in[0];
    const float* gw = (const float*)d_in[1];
    const float* Wg = (const float*)d_in[2];
    const float* Wu = (const float*)d_in[3];
    const float* Wd = (const float*)d_in[4];
    const float* Sg = (const float*)d_in[5];
    const float* Su = (const float*)d_in[6];
    const float* Sd = (const float*)d_in[7];
    float* y = (float*)d_out;

    void *p_ti, *p_tw, *p_g, *p_u, *p_h, *p_ob, *p_gs, *p_us, *p_hs, *p_ys;
    cudaGetSymbolAddress(&p_ti, g_topk_i);  cudaGetSymbolAddress(&p_tw, g_topk_w);
    cudaGetSymbolAddress(&p_g,  g_gbuf);    cudaGetSymbolAddress(&p_u,  g_ubuf);
    cudaGetSymbolAddress(&p_h,  g_hbuf);    cudaGetSymbolAddress(&p_ob, g_outb);
    cudaGetSymbolAddress(&p_gs, g_gs);      cudaGetSymbolAddress(&p_us, g_us);
    cudaGetSymbolAddress(&p_hs, g_hs);      cudaGetSymbolAddress(&p_ys, g_ys);

    cudaFuncSetAttribute(fg_gemm<true>,  cudaFuncAttributeMaxDynamicSharedMemorySize, SMEM_TOT);
    cudaFuncSetAttribute(fg_gemm<false>, cudaFuncAttributeMaxDynamicSharedMemorySize, SMEM_TOT);

    // 1) gate + dispatch
    gate_kernel<<<TT, 64>>>(x, gw, (int*)p_ti, (float*)p_tw);
    zero_cnt_kernel<<<1, 64>>>();
    dispatch_kernel<<<(NPAIR + 255)/256, 256>>>((const int*)p_ti);

    // 2) routed GEMM1: g and u (A = gathered x rows fp32, K = HH)
    fg_gemm<true><<<dim3(MM/128, CC/128, EE), 256, SMEM_TOT>>>(
        x, Wg, (float*)p_g, HH, KK, (long long)MM*HH, MM, 0);
    fg_gemm<true><<<dim3(MM/128, CC/128, EE), 256, SMEM_TOT>>>(
        x, Wu, (float*)p_u, HH, KK, (long long)MM*HH, MM, 0);

    // 3) swiglu -> h (fp32)
    {
        size_t n4 = (size_t)NPAIR*MM/4;
        swiglu_kernel<<<(int)((n4 + 255)/256), 256>>>((const float*)p_g, (const float*)p_u,
                                                      (float*)p_h, n4);
    }

    // 4) routed GEMM2 (Wd): A = h rows by pair id, K = MM
    fg_gemm<true><<<dim3(HH/128, CC/128, EE), 256, SMEM_TOT>>>(
        (const float*)p_h, Wd, (float*)p_ob, MM, 1, (long long)HH*MM, HH, 0);

    // 5) shared expert g,u (K = HH)
    fg_gemm<false><<<dim3(MSS/128, TT/128, 1), 256, SMEM_TOT>>>(
        x, Sg, (float*)p_gs, HH, 1, 0LL, MSS, TT);
    fg_gemm<false><<<dim3(MSS/128, TT/128, 1), 256, SMEM_TOT>>>(
        x, Su, (float*)p_us, HH, 1, 0LL, MSS, TT);

    // 6) shared swiglu
    {
        size_t n4 = (size_t)TT*MSS/4;
        swiglu_kernel<<<(int)((n4 + 255)/256), 256>>>((const float*)p_gs, (const float*)p_us,
                                                      (float*)p_hs, n4);
    }

    // 7) shared GEMM2 (Sd, K = MSS)
    fg_gemm<false><<<dim3(HH/128, TT/128, 1), 256, SMEM_TOT>>>(
        (const float*)p_hs, Sd, (float*)p_ys, MSS, 1, 0LL, HH, TT);

    // 8) combine
    combine_kernel<<<TT, 256>>>((const float*)p_ob, (const float*)p_ys,
                                (const float*)p_tw, y);
}

// round 8
// speedup vs baseline: 1.2529x; 1.1112x over previous
#include <cuda_runtime.h>
#include <cuda_bf16.h>
#include <math.h>
#include <stdint.h>

// ---------------- problem constants ----------------
#define TT   4096
#define HH   2048
#define EE   64
#define MM   1408
#define MSS  2816
#define KK   6
#define CC   768
#define NGG  8
#define TGG  3
#define NPAIR (TT*KK)        // 24576

// ---------------- device scratch ----------------
__device__ int   g_topk_i[NPAIR];
__device__ float g_topk_w[NPAIR];
__device__ int   g_cnt[EE];
__device__ int   g_lists[EE*CC];
__device__ float g_gbuf[(size_t)NPAIR*MM];
__device__ float g_ubuf[(size_t)NPAIR*MM];
__device__ float g_hbuf[(size_t)NPAIR*MM];
__device__ float g_outb[(size_t)NPAIR*HH];
__device__ float g_gs[(size_t)TT*MSS];
__device__ float g_us[(size_t)TT*MSS];
__device__ float g_hs[(size_t)TT*MSS];
__device__ float g_ys[(size_t)TT*HH];

// ---------------- gate ----------------
__global__ void gate_kernel(const float* __restrict__ x,
                            const float* __restrict__ gw,
                            int* __restrict__ ti, float* __restrict__ tw)
{
    int t = blockIdx.x;
    __shared__ float xs[HH];
    __shared__ float sc[EE];
    for (int i = threadIdx.x; i < HH; i += 64) xs[i] = x[(size_t)t*HH + i];
    __syncthreads();
    {
        int e = threadIdx.x;
        const float* w = gw + (size_t)e * HH;
        float acc = 0.f;
        #pragma unroll 8
        for (int h = 0; h < HH; ++h) acc = fmaf(xs[h], w[h], acc);
        sc[e] = acc;
    }
    __syncthreads();
    if (threadIdx.x == 0) {
        float mx = sc[0];
        for (int e = 1; e < EE; ++e) mx = fmaxf(mx, sc[e]);
        float sum = 0.f;
        for (int e = 0; e < EE; ++e) { float v = expf(sc[e] - mx); sc[e] = v; sum += v; }
        float inv = 1.f / sum;
        for (int e = 0; e < EE; ++e) sc[e] *= inv;
        float gs[NGG];
        for (int g = 0; g < NGG; ++g) {
            float m = sc[g*8];
            for (int j = 1; j < 8; ++j) m = fmaxf(m, sc[g*8 + j]);
            gs[g] = m;
        }
        unsigned gsel = 0;
        for (int it = 0; it < TGG; ++it) {
            int best = -1; float bv = -1e30f;
            for (int g = 0; g < NGG; ++g)
                if (!((gsel >> g) & 1u) && gs[g] > bv) { bv = gs[g]; best = g; }
            gsel |= 1u << best;
        }
        unsigned long long used = 0ull;
        for (int kk = 0; kk < KK; ++kk) {
            int best = -1; float bv = -1e30f;
            for (int e = 0; e < EE; ++e) {
                if (!((gsel >> (e >> 3)) & 1u)) continue;
                if ((used >> e) & 1ull) continue;
                if (sc[e] > bv) { bv = sc[e]; best = e; }
            }
            used |= 1ull << best;
            ti[t*KK + kk] = best;
            tw[t*KK + kk] = sc[best];
        }
    }
}

__global__ void zero_cnt_kernel() { if (threadIdx.x < EE) g_cnt[threadIdx.x] = 0; }

__global__ void dispatch_kernel(const int* __restrict__ ti)
{
    int p = blockIdx.x * blockDim.x + threadIdx.x;
    if (p >= NPAIR) return;
    int e = ti[p];
    int r = atomicAdd(&g_cnt[e], 1);
    if (r < CC) g_lists[e*CC + r] = p;
}

// ---------------- swiglu (fp32 out) ----------------
__global__ void swiglu_kernel(const float* __restrict__ g,
                              const float* __restrict__ u,
                              float* __restrict__ h, size_t n4)
{
    size_t i = (size_t)blockIdx.x * blockDim.x + threadIdx.x;
    size_t stride = (size_t)gridDim.x * blockDim.x;
    for (; i < n4; i += stride) {
        float4 gv = ((const float4*)g)[i];
        float4 uv = ((const float4*)u)[i];
        float4 r;
        r.x = (gv.x / (1.f + expf(-gv.x))) * uv.x;
        r.y = (gv.y / (1.f + expf(-gv.y))) * uv.y;
        r.z = (gv.z / (1.f + expf(-gv.z))) * uv.z;
        r.w = (gv.w / (1.f + expf(-gv.w))) * uv.w;
        ((float4*)h)[i] = r;
    }
}

// ======================= split-MMA GEMM, fused fp32->bf16 hi/lo =========
// CTA 128x128, k-chunk 32, 256 threads (8 warps of 64x32), 2-stage smem,
// register-lean (frag reuse + phased staging) for 2 CTAs/SM.

#define LDSM4(R, addr) asm volatile( \
    "ldmatrix.sync.aligned.m8n8.x4.shared.b16 {%0,%1,%2,%3},[%4];" \
    : "=r"((R)[0]), "=r"((R)[1]), "=r"((R)[2]), "=r"((R)[3]) : "r"(addr))
#define LDSM2(R, addr) asm volatile( \
    "ldmatrix.sync.aligned.m8n8.x2.shared.b16 {%0,%1},[%2];" \
    : "=r"((R)[0]), "=r"((R)[1]) : "r"(addr))
#define MMA16816(C, A, B) asm volatile( \
    "mma.sync.aligned.m16n8k16.row.col.f32.bf16.bf16.f32 " \
    "{%0,%1,%2,%3},{%4,%5,%6,%7},{%8,%9},{%0,%1,%2,%3};" \
    : "+f"((C)[0]), "+f"((C)[1]), "+f"((C)[2]), "+f"((C)[3]) \
    : "r"((A)[0]), "r"((A)[1]), "r"((A)[2]), "r"((A)[3]), "r"((B)[0]), "r"((B)[1]))

// stage layout (bytes): Ahi 0 (128*80), Alo 10240, Bhi 20480 (128*80), Blo 30720
#define STAGE_B 40960
#define SMEM_TOT (2*STAGE_B + 1024)

__device__ __forceinline__ uint32_t b2u(__nv_bfloat162 v){ return *(uint32_t*)&v; }
__device__ __forceinline__ void cvt8(float4 A, float4 B, uint4& hi, uint4& lo){
    __nv_bfloat162 h0 = __floats2bfloat162_rn(A.x, A.y);
    __nv_bfloat162 h1 = __floats2bfloat162_rn(A.z, A.w);
    __nv_bfloat162 h2 = __floats2bfloat162_rn(B.x, B.y);
    __nv_bfloat162 h3 = __floats2bfloat162_rn(B.z, B.w);
    hi = make_uint4(b2u(h0), b2u(h1), b2u(h2), b2u(h3));
    __nv_bfloat162 l0 = __floats2bfloat162_rn(A.x - __low2float(h0), A.y - __high2float(h0));
    __nv_bfloat162 l1 = __floats2bfloat162_rn(A.z - __low2float(h1), A.w - __high2float(h1));
    __nv_bfloat162 l2 = __floats2bfloat162_rn(B.x - __low2float(h2), B.y - __high2float(h2));
    __nv_bfloat162 l3 = __floats2bfloat162_rn(B.z - __low2float(h3), B.w - __high2float(h3));
    lo = make_uint4(b2u(l0), b2u(l1), b2u(l2), b2u(l3));
}

template<bool GATHER>
__global__ void __launch_bounds__(256, 2)
fg_gemm(const float* __restrict__ A,
        const float* __restrict__ Bg,
        float* __restrict__ Out,
        int Kd, int adiv, long long bstride, int ldo, int nrows_fixed)
{
    extern __shared__ char smem[];
    const int e = blockIdx.z;
    int nrows; const int* mylist = nullptr;
    if (GATHER){ nrows = min(g_cnt[e], CC); mylist = &g_lists[e*CC]; }
    else nrows = nrows_fixed;
    const int m0 = blockIdx.y*128;
    if (m0 >= nrows) return;
    const int n0 = blockIdx.x*128;
    const float* B = Bg + (size_t)e*bstride;

    int* rowA = (int*)(smem + 2*STAGE_B);
    int* rowO = (int*)(smem + 2*STAGE_B + 512);
    const int tid = threadIdx.x;
    if (tid < 128){
        int r = m0 + tid;
        if (r < nrows){
            if (GATHER){ int p = mylist[r]; rowA[tid] = p/adiv; rowO[tid] = p; }
            else       { rowA[tid] = r;      rowO[tid] = r; }
        } else { rowA[tid] = -1; rowO[tid] = -1; }
    }
    __syncthreads();

    // loaders: row = tid>>1 (0..127), half = tid&1 (16 floats each)
    const int lrow = tid >> 1, half = tid & 1;
    int ra = rowA[lrow]; if (ra < 0) ra = 0;
    const float* pa = A + (size_t)ra*Kd + half*16;
    const float* pb = B + (size_t)(n0 + lrow)*Kd + half*16;
    char* sa = smem + lrow*80 + half*32;
    char* sb = smem + 20480 + lrow*80 + half*32;

    float4 s0, s1, s2, s3;     // shared staging for A-phase then B-phase
    auto ldgA = [&](int kt){
        const int k0 = kt*32;
        s0 = *(const float4*)(pa + k0);
        s1 = *(const float4*)(pa + k0 + 4);
        s2 = *(const float4*)(pa + k0 + 8);
        s3 = *(const float4*)(pa + k0 + 12);
    };
    auto ldgB = [&](int kt){
        const int k0 = kt*32;
        s0 = *(const float4*)(pb + k0);
        s1 = *(const float4*)(pb + k0 + 4);
        s2 = *(const float4*)(pb + k0 + 8);
        s3 = *(const float4*)(pb + k0 + 12);
    };
    auto cvt_stsA = [&](int buf){
        uint4 hi, lo;
        char* da = sa + buf*STAGE_B;
        cvt8(s0, s1, hi, lo);
        *(uint4*)(da)            = hi;
        *(uint4*)(da + 10240)    = lo;
        cvt8(s2, s3, hi, lo);
        *(uint4*)(da + 16)       = hi;
        *(uint4*)(da + 10256)    = lo;
    };
    auto cvt_stsB = [&](int buf){
        uint4 hi, lo;
        char* db = sb + buf*STAGE_B;
        cvt8(s0, s1, hi, lo);
        *(uint4*)(db)            = hi;
        *(uint4*)(db + 10240)    = lo;
        cvt8(s2, s3, hi, lo);
        *(uint4*)(db + 16)       = hi;
        *(uint4*)(db + 10256)    = lo;
    };

    const int lane = tid & 31;
    const int wid  = tid >> 5;
    const int wm = (wid & 1) * 64;       // warp tile 64x32
    const int wn = (wid >> 1) * 32;

    float acc[4][4][4];
    #pragma unroll
    for (int i = 0; i < 4; ++i)
        #pragma unroll
        for (int j = 0; j < 4; ++j)
            #pragma unroll
            for (int c = 0; c < 4; ++c) acc[i][j][c] = 0.f;

    const uint32_t smem_u = (uint32_t)__cvta_generic_to_shared(smem);
    const uint32_t aoff = (uint32_t)((wm + (lane & 7) + ((lane >> 3) & 1) * 8) * 80
                                     + (lane >> 4) * 16);
    const uint32_t boff = (uint32_t)(20480 + (wn + (lane & 7)) * 80 + ((lane >> 3) & 1) * 16);

    // one kk section: B-lo -> A-hi·B-lo ; B-hi -> A-hi·B-hi ; A-lo -> A-lo·B-hi
    auto mma_kk = [&](uint32_t b, int kk){
        const uint32_t kb = kk * 32;
        uint32_t af[4][4], bf[4][2];
        #pragma unroll
        for (int ni = 0; ni < 4; ++ni)
            LDSM2(bf[ni], b + 10240 + boff + kb + ni * (8*80));       // B lo
        #pragma unroll
        for (int mi = 0; mi < 4; ++mi)
            LDSM4(af[mi], b + aoff + kb + mi * (16*80));              // A hi
        #pragma unroll
        for (int mi = 0; mi < 4; ++mi)
            #pragma unroll
            for (int ni = 0; ni < 4; ++ni)
                MMA16816(acc[mi][ni], af[mi], bf[ni]);                // ah*bl
        #pragma unroll
        for (int ni = 0; ni < 4; ++ni)
            LDSM2(bf[ni], b + boff + kb + ni * (8*80));               // B hi
        #pragma unroll
        for (int mi = 0; mi < 4; ++mi)
            #pragma unroll
            for (int ni = 0; ni < 4; ++ni)
                MMA16816(acc[mi][ni], af[mi], bf[ni]);                // ah*bh
        #pragma unroll
        for (int mi = 0; mi < 4; ++mi)
            LDSM4(af[mi], b + 10240 + aoff + kb + mi * (16*80));      // A lo
        #pragma unroll
        for (int mi = 0; mi < 4; ++mi)
            #pragma unroll
            for (int ni = 0; ni < 4; ++ni)
                MMA16816(acc[mi][ni], af[mi], bf[ni]);                // al*bh
    };

    const int KT = Kd / 32;
    // prologue: fill stage 0
    ldgA(0); cvt_stsA(0);
    ldgB(0); cvt_stsB(0);

    for (int kt = 0; kt < KT; ++kt){
        __syncthreads();
        const uint32_t b = smem_u + (kt & 1) * STAGE_B;
        const int nb = (kt + 1) & 1;
        if (kt + 1 < KT) ldgA(kt + 1);
        mma_kk(b, 0);
        if (kt + 1 < KT) { cvt_stsA(nb); ldgB(kt + 1); }
        mma_kk(b, 1);
        if (kt + 1 < KT) cvt_stsB(nb);
    }

    // epilogue
    const int g4 = lane >> 2, tig = lane & 3;
    #pragma unroll
    for (int mi = 0; mi < 4; ++mi){
        int r0 = wm + mi*16 + g4;
        int r1 = r0 + 8;
        int o0 = rowO[r0], o1 = rowO[r1];
        #pragma unroll
        for (int ni = 0; ni < 4; ++ni){
            int cc = n0 + wn + ni*8 + tig*2;
            if (o0 >= 0)
                *(float2*)(Out + (size_t)o0*ldo + cc) = make_float2(acc[mi][ni][0], acc[mi][ni][1]);
            if (o1 >= 0)
                *(float2*)(Out + (size_t)o1*ldo + cc) = make_float2(acc[mi][ni][2], acc[mi][ni][3]);
        }
    }
}

// ---------------- combine ----------------
__global__ void combine_kernel(const float* __restrict__ ob,
                               const float* __restrict__ ys,
                               const float* __restrict__ tw,
                               float* __restrict__ y)
{
    int t = blockIdx.x;
    for (int c = threadIdx.x; c < HH; c += blockDim.x) {
        float acc = ys[(size_t)t*HH + c];
        #pragma unroll
        for (int k = 0; k < KK; ++k) {
            int p = t*KK + k;
            acc = fmaf(tw[p], ob[(size_t)p*HH + c], acc);
        }
        y[(size_t)t*HH + c] = acc;
    }
}

// ---------------- launch ----------------
extern "C" void kernel_launch(void* const* d_in, const int* in_sizes, int n_in,
                              void* d_out, int out_size)
{
    const float* x  = (const float*)d_in[0];
    const float* gw = (const float*)d_in[1];
    const float* Wg = (const float*)d_in[2];
    const float* Wu = (const float*)d_in[3];
    const float* Wd = (const float*)d_in[4];
    const float* Sg = (const float*)d_in[5];
    const float* Su = (const float*)d_in[6];
    const float* Sd = (const float*)d_in[7];
    float* y = (float*)d_out;

    void *p_ti, *p_tw, *p_g, *p_u, *p_h, *p_ob, *p_gs, *p_us, *p_hs, *p_ys;
    cudaGetSymbolAddress(&p_ti, g_topk_i);  cudaGetSymbolAddress(&p_tw, g_topk_w);
    cudaGetSymbolAddress(&p_g,  g_gbuf);    cudaGetSymbolAddress(&p_u,  g_ubuf);
    cudaGetSymbolAddress(&p_h,  g_hbuf);    cudaGetSymbolAddress(&p_ob, g_outb);
    cudaGetSymbolAddress(&p_gs, g_gs);      cudaGetSymbolAddress(&p_us, g_us);
    cudaGetSymbolAddress(&p_hs, g_hs);      cudaGetSymbolAddress(&p_ys, g_ys);

    cudaFuncSetAttribute(fg_gemm<true>,  cudaFuncAttributeMaxDynamicSharedMemorySize, SMEM_TOT);
    cudaFuncSetAttribute(fg_gemm<false>, cudaFuncAttributeMaxDynamicSharedMemorySize, SMEM_TOT);

    // 1) gate + dispatch
    gate_kernel<<<TT, 64>>>(x, gw, (int*)p_ti, (float*)p_tw);
    zero_cnt_kernel<<<1, 64>>>();
    dispatch_kernel<<<(NPAIR + 255)/256, 256>>>((const int*)p_ti);

    // 2) routed GEMM1: g and u (A = gathered x rows fp32, K = HH)
    fg_gemm<true><<<dim3(MM/128, CC/128, EE), 256, SMEM_TOT>>>(
        x, Wg, (float*)p_g, HH, KK, (long long)MM*HH, MM, 0);
    fg_gemm<true><<<dim3(MM/128, CC/128, EE), 256, SMEM_TOT>>>(
        x, Wu, (float*)p_u, HH, KK, (long long)MM*HH, MM, 0);

    // 3) swiglu -> h (fp32)
    {
        size_t n4 = (size_t)NPAIR*MM/4;
        swiglu_kernel<<<(int)((n4 + 255)/256), 256>>>((const float*)p_g, (const float*)p_u,
                                                      (float*)p_h, n4);
    }

    // 4) routed GEMM2 (Wd): A = h rows by pair id, K = MM
    fg_gemm<true><<<dim3(HH/128, CC/128, EE), 256, SMEM_TOT>>>(
        (const float*)p_h, Wd, (float*)p_ob, MM, 1, (long long)HH*MM, HH, 0);

    // 5) shared expert g,u (K = HH)
    fg_gemm<false><<<dim3(MSS/128, TT/128, 1), 256, SMEM_TOT>>>(
        x, Sg, (float*)p_gs, HH, 1, 0LL, MSS, TT);
    fg_gemm<false><<<dim3(MSS/128, TT/128, 1), 256, SMEM_TOT>>>(
        x, Su, (float*)p_us, HH, 1, 0LL, MSS, TT);

    // 6) shared swiglu
    {
        size_t n4 = (size_t)TT*MSS/4;
        swiglu_kernel<<<(int)((n4 + 255)/256), 256>>>((const float*)p_gs, (const float*)p_us,
                                                      (float*)p_hs, n4);
    }

    // 7) shared GEMM2 (Sd, K = MSS)
    fg_gemm<false><<<dim3(HH/128, TT/128, 1), 256, SMEM_TOT>>>(
        (const float*)p_hs, Sd, (float*)p_ys, MSS, 1, 0LL, HH, TT);

    // 8) combine
    combine_kernel<<<TT, 256>>>((const float*)p_ob, (const float*)p_ys,
                                (const float*)p_tw, y);
}